// round 3
// baseline (speedup 1.0000x reference)
#include <cuda_runtime.h>

#define NMAX 100000
#define EMAX 1600000
#define F_IN 256
#define C1 32
#define C2 16
#define CHUNK 1024

// ---------------- scratch (device globals: allocation-free) ----------------
__device__ float g_deg[NMAX];
__device__ int   g_cnt[NMAX];      // in-degree count incl. self loop
__device__ int   g_intra[NMAX];    // intra-chunk exclusive scan
__device__ int   g_chunk[(NMAX + CHUNK - 1) / CHUNK];
__device__ int   g_chunkoff[(NMAX + CHUNK - 1) / CHUNK];
__device__ int   g_ptr[NMAX];      // CSR start
__device__ int   g_ptrw[NMAX];     // working atomic cursor
__device__ int2  g_se[EMAX + NMAX]; // sorted edges: {row, norm_bits}
__device__ float g_H1[(size_t)NMAX * C1];
__device__ float g_out1[(size_t)NMAX * C1];
__device__ float g_H2[(size_t)NMAX * C2];
__device__ int   g_is64;

// ---------------- k0: zero deg, cnt=1 (self loop), dtype detect ------------
__global__ void k0_init(const int* __restrict__ ei32, int N, int E) {
    if (blockIdx.x == 0 && threadIdx.x < 32) {
        int ok = 1;
#pragma unroll
        for (int s = 0; s < 2; s++) {
            int idx = threadIdx.x + 32 * s;
            if (idx < E && idx < 64 && ei32[2 * idx + 1] != 0) ok = 0;
        }
        unsigned m = __ballot_sync(0xffffffffu, ok);
        if (threadIdx.x == 0) g_is64 = (m == 0xffffffffu) ? 1 : 0;
    }
    int i = blockIdx.x * blockDim.x + threadIdx.x;
    if (i < N) { g_deg[i] = 0.f; g_cnt[i] = 1; }
}

// ---------------- k1: weighted degree + histogram over col -----------------
__global__ void k1_deg_hist(const void* __restrict__ ei, const float* __restrict__ w, int E) {
    int e = blockIdx.x * blockDim.x + threadIdx.x;
    if (e >= E) return;
    int c;
    if (g_is64) c = (int)((const long long*)ei)[(size_t)E + e];
    else        c = ((const int*)ei)[E + e];
    atomicAdd(&g_deg[c], w[e]);
    atomicAdd(&g_cnt[c], 1);
}

// ---------------- k2: GEMM1 H1 = x @ W1, x staged in smem (coalesced) ------
// 16 rows/block, 8 threads/row (4 outputs each), packed f32x2 FMA.
__global__ void k2_gemm1(const float* __restrict__ x, const float* __restrict__ W1, int N) {
    __shared__ float sX[16 * F_IN];   // 16 KB
    __shared__ float sW[F_IN * C1];   // 32 KB
    int tid = threadIdx.x;            // 128 threads
    // stage W1 (coalesced)
    for (int i = tid; i < F_IN * C1 / 4; i += 128)
        ((float4*)sW)[i] = ((const float4*)W1)[i];
    // stage 16 rows of x (coalesced)
    size_t base = (size_t)blockIdx.x * 16 * F_IN;
    int maxv = N * F_IN / 4 - (int)(base / 4);
    for (int i = tid; i < 16 * F_IN / 4; i += 128)
        ((float4*)sX)[i] = (i < maxv) ? ((const float4*)(x + base))[i]
                                      : make_float4(0.f, 0.f, 0.f, 0.f);
    __syncthreads();

    int row = tid >> 3, js = tid & 7;
    int grow = blockIdx.x * 16 + row;
    if (grow >= N) return;

    unsigned long long acc0 = 0ull, acc1 = 0ull;
    const float4* xr = (const float4*)&sX[row * F_IN];
    const unsigned long long* wp = (const unsigned long long*)sW;
#pragma unroll 4
    for (int k4 = 0; k4 < F_IN / 4; k4++) {
        float4 xv = xr[k4];
        float xs[4] = {xv.x, xv.y, xv.z, xv.w};
#pragma unroll
        for (int s = 0; s < 4; s++) {
            unsigned long long xx;
            asm("mov.b64 %0, {%1, %1};" : "=l"(xx) : "f"(xs[s]));
            int wi = (k4 * 4 + s) * (C1 / 2) + js * 2;
            asm("fma.rn.f32x2 %0, %1, %2, %0;" : "+l"(acc0) : "l"(wp[wi]), "l"(xx));
            asm("fma.rn.f32x2 %0, %1, %2, %0;" : "+l"(acc1) : "l"(wp[wi + 1]), "l"(xx));
        }
    }
    float r0, r1, r2, r3;
    asm("mov.b64 {%0, %1}, %2;" : "=f"(r0), "=f"(r1) : "l"(acc0));
    asm("mov.b64 {%0, %1}, %2;" : "=f"(r2), "=f"(r3) : "l"(acc1));
    *(float4*)&g_H1[(size_t)grow * C1 + js * 4] = make_float4(r0, r1, r2, r3);
}

// ---------------- k3a/b/c: exclusive scan of g_cnt -> g_ptr ----------------
__global__ void k3a_scan(int N) {
    __shared__ int s[CHUNK];
    int tid = threadIdx.x;
    int i = blockIdx.x * CHUNK + tid;
    int v = (i < N) ? g_cnt[i] : 0;
    s[tid] = v;
    __syncthreads();
#pragma unroll
    for (int off = 1; off < CHUNK; off <<= 1) {
        int t = (tid >= off) ? s[tid - off] : 0;
        __syncthreads();
        s[tid] += t;
        __syncthreads();
    }
    if (i < N) g_intra[i] = s[tid] - v;
    if (tid == CHUNK - 1) g_chunk[blockIdx.x] = s[tid];
}

__global__ void k3b_scan_chunks(int nch) {
    __shared__ int s[128];
    int tid = threadIdx.x;
    s[tid] = (tid < nch) ? g_chunk[tid] : 0;
    __syncthreads();
    if (tid == 0) {
        int run = 0;
        for (int j = 0; j < nch; j++) { int t = s[j]; s[j] = run; run += t; }
    }
    __syncthreads();
    if (tid < nch) g_chunkoff[tid] = s[tid];
}

__global__ void k3c_finish(int N) {
    int i = blockIdx.x * blockDim.x + threadIdx.x;
    if (i >= N) return;
    int p = g_intra[i] + g_chunkoff[i >> 10];
    g_ptr[i] = p;
    g_ptrw[i] = p;
}

// ---------------- k4: place edges into CSR buckets with norm ---------------
__global__ void k4_place(const void* __restrict__ ei, const float* __restrict__ w,
                         int E, int N) {
    int e = blockIdx.x * blockDim.x + threadIdx.x;
    if (e >= E + N) return;
    int r, c; float wt;
    if (e < E) {
        if (g_is64) {
            const long long* p = (const long long*)ei;
            r = (int)p[e]; c = (int)p[(size_t)E + e];
        } else {
            const int* p = (const int*)ei;
            r = p[e]; c = p[E + e];
        }
        wt = w[e];
    } else {
        r = c = e - E; wt = 1.f;
    }
    float nrm = rsqrtf(g_deg[r] + 1.f) * wt * rsqrtf(g_deg[c] + 1.f);
    int pos = atomicAdd(&g_ptrw[c], 1);
    g_se[pos] = make_int2(r, __float_as_int(nrm));
}

// ---------------- k5: gather layer 1: out1[n] = sum norm*H1[row] -----------
// 8 threads per node, 4 cols each; no atomics, coalesced store.
__global__ void k5_gather1(int N) {
    int tid = threadIdx.x;
    int node = blockIdx.x * 32 + (tid >> 3);
    if (node >= N) return;
    int lane = tid & 7;
    int start = g_ptr[node];
    int end = start + g_cnt[node];
    float ax = 0.f, ay = 0.f, az = 0.f, aw = 0.f;
    for (int e = start; e < end; e++) {
        int2 se = g_se[e];
        float nrm = __int_as_float(se.y);
        float4 h = *(const float4*)&g_H1[(size_t)se.x * C1 + lane * 4];
        ax += nrm * h.x; ay += nrm * h.y; az += nrm * h.z; aw += nrm * h.w;
    }
    *(float4*)&g_out1[(size_t)node * C1 + lane * 4] = make_float4(ax, ay, az, aw);
}

// ---------------- k6: H2 = relu(out1 + b1) @ W2 ----------------------------
__global__ void k6_gemm2(const float* __restrict__ b1, const float* __restrict__ W2, int N) {
    __shared__ float sW[C1 * C2];
    __shared__ float sb[C1];
    for (int i = threadIdx.x; i < C1 * C2; i += blockDim.x) sW[i] = W2[i];
    if (threadIdx.x < C1) sb[threadIdx.x] = b1[threadIdx.x];
    __syncthreads();
    int row = blockIdx.x * blockDim.x + threadIdx.x;
    if (row >= N) return;
    const float4* in = (const float4*)&g_out1[(size_t)row * C1];
    float h[C1];
#pragma unroll
    for (int k4 = 0; k4 < C1 / 4; k4++) {
        float4 v = in[k4];
        h[4 * k4 + 0] = fmaxf(v.x + sb[4 * k4 + 0], 0.f);
        h[4 * k4 + 1] = fmaxf(v.y + sb[4 * k4 + 1], 0.f);
        h[4 * k4 + 2] = fmaxf(v.z + sb[4 * k4 + 2], 0.f);
        h[4 * k4 + 3] = fmaxf(v.w + sb[4 * k4 + 3], 0.f);
    }
    float acc[C2];
#pragma unroll
    for (int j = 0; j < C2; j++) acc[j] = 0.f;
#pragma unroll
    for (int k = 0; k < C1; k++) {
        const float* wk = &sW[k * C2];
#pragma unroll
        for (int j = 0; j < C2; j++) acc[j] += h[k] * wk[j];
    }
    float4* o = (float4*)&g_H2[(size_t)row * C2];
#pragma unroll
    for (int j4 = 0; j4 < C2 / 4; j4++)
        o[j4] = make_float4(acc[4 * j4], acc[4 * j4 + 1], acc[4 * j4 + 2], acc[4 * j4 + 3]);
}

// ---------------- k7: gather layer 2: out[n] = b2 + sum norm*H2[row] -------
// 4 threads per node, 4 cols each.
__global__ void k7_gather2(float* __restrict__ out, const float* __restrict__ b2, int N) {
    int tid = threadIdx.x;
    int node = blockIdx.x * 64 + (tid >> 2);
    if (node >= N) return;
    int lane = tid & 3;
    float4 b = __ldg((const float4*)b2 + lane);
    int start = g_ptr[node];
    int end = start + g_cnt[node];
    float ax = b.x, ay = b.y, az = b.z, aw = b.w;
    for (int e = start; e < end; e++) {
        int2 se = g_se[e];
        float nrm = __int_as_float(se.y);
        float4 h = *(const float4*)&g_H2[(size_t)se.x * C2 + lane * 4];
        ax += nrm * h.x; ay += nrm * h.y; az += nrm * h.z; aw += nrm * h.w;
    }
    *(float4*)&out[(size_t)node * C2 + lane * 4] = make_float4(ax, ay, az, aw);
}

// ---------------- launch ----------------------------------------------------
extern "C" void kernel_launch(void* const* d_in, const int* in_sizes, int n_in,
                              void* d_out, int out_size) {
    const float* x  = (const float*)d_in[0];
    const void*  ei = d_in[1];
    const float* w  = (const float*)d_in[2];
    const float* W1 = (const float*)d_in[3];
    const float* b1 = (const float*)d_in[4];
    const float* W2 = (const float*)d_in[5];
    const float* b2 = (const float*)d_in[6];
    float* out = (float*)d_out;

    int N = in_sizes[0] / F_IN;
    int E = in_sizes[2];
    int T = E + N;
    int nch = (N + CHUNK - 1) / CHUNK;

    k0_init<<<(N + 255) / 256, 256>>>((const int*)ei, N, E);
    k1_deg_hist<<<(E + 255) / 256, 256>>>(ei, w, E);
    k2_gemm1<<<(N + 15) / 16, 128>>>(x, W1, N);
    k3a_scan<<<nch, CHUNK>>>(N);
    k3b_scan_chunks<<<1, 128>>>(nch);
    k3c_finish<<<(N + 255) / 256, 256>>>(N);
    k4_place<<<(T + 255) / 256, 256>>>(ei, w, E, N);
    k5_gather1<<<(N + 31) / 32, 256>>>(N);
    k6_gemm2<<<(N + 255) / 256, 256>>>(b1, W2, N);
    k7_gather2<<<(N + 63) / 64, 256>>>(out, b2, N);
}

// round 4
// speedup vs baseline: 1.3521x; 1.3521x over previous
#include <cuda_runtime.h>
#include <cuda_fp16.h>

#define NMAX 100000
#define EMAX 1600000
#define F_IN 256
#define C1 32
#define C2 16

// ---------------- scratch (device globals: allocation-free) ----------------
__device__ float  g_deg[NMAX];
__device__ int2   g_rc[EMAX + NMAX];
__device__ float  g_norm[EMAX + NMAX];
__device__ __half g_H1[(size_t)NMAX * C1];   // x @ W1, fp16
__device__ float  g_out1[(size_t)NMAX * C1]; // layer-1 aggregation, fp32
__device__ __half g_H2[(size_t)NMAX * C2];   // relu(out1+b1) @ W2, fp16
__device__ int    g_is64;

// ---------------- k0: init + parallel dtype detect -------------------------
// int64 edge_index with values < 2^31 => every odd 32-bit word is 0.
__global__ void k0_init(float* __restrict__ out, const float* __restrict__ b2,
                        const int* __restrict__ ei32, int N, int E) {
    if (blockIdx.x == 0 && threadIdx.x < 32) {
        int ok = 1;
#pragma unroll
        for (int s = 0; s < 2; s++) {
            int idx = threadIdx.x + 32 * s;
            if (idx < E && idx < 64 && ei32[2 * idx + 1] != 0) ok = 0;
        }
        unsigned m = __ballot_sync(0xffffffffu, ok);
        if (threadIdx.x == 0) g_is64 = (m == 0xffffffffu) ? 1 : 0;
    }
    int i = blockIdx.x * blockDim.x + threadIdx.x;
    if (i < N * C1) g_out1[i] = 0.f;
    if (i < N)      g_deg[i]  = 0.f;
    if (i < N * C2) out[i]    = b2[i & (C2 - 1)];
}

// ---------------- k1: weighted in-degree -----------------------------------
__global__ void k1_deg(const void* __restrict__ ei, const float* __restrict__ w, int E) {
    int e = blockIdx.x * blockDim.x + threadIdx.x;
    if (e >= E) return;
    int c;
    if (g_is64) c = (int)((const long long*)ei)[(size_t)E + e];
    else        c = ((const int*)ei)[E + e];
    atomicAdd(&g_deg[c], w[e]);
}

// ---------------- k2: edge normalization (self loops as virtual edges) -----
__global__ void k2_pre(const void* __restrict__ ei, const float* __restrict__ w,
                       int E, int N) {
    int e = blockIdx.x * blockDim.x + threadIdx.x;
    if (e >= E + N) return;
    int r, c; float wt;
    if (e < E) {
        if (g_is64) {
            const long long* p = (const long long*)ei;
            r = (int)p[e]; c = (int)p[(size_t)E + e];
        } else {
            const int* p = (const int*)ei;
            r = p[e]; c = p[E + e];
        }
        wt = w[e];
    } else {
        r = c = e - E; wt = 1.f;
    }
    g_rc[e] = make_int2(r, c);
    g_norm[e] = rsqrtf(g_deg[r] + 1.f) * wt * rsqrtf(g_deg[c] + 1.f);
}

// ---------------- k3: GEMM1  H1 = fp16(x @ W1)  (4th launch -> profiled) ---
// Thread per row; W1 staged in smem as packed u64 pairs -> LDS.128 broadcast
// (1 wavefront/instr), x via LDG.128; packed fma.rn.f32x2 accumulators.
__global__ void __launch_bounds__(256) k3_gemm1(const float* __restrict__ x,
                                                const float* __restrict__ W1, int N) {
    __shared__ float sW[F_IN * C1];  // 32 KB
    for (int i = threadIdx.x; i < F_IN * C1 / 4; i += 256)
        ((float4*)sW)[i] = __ldg((const float4*)W1 + i);
    __syncthreads();
    int row = blockIdx.x * 256 + threadIdx.x;
    if (row >= N) return;

    unsigned long long acc[C1 / 2];
#pragma unroll
    for (int j = 0; j < C1 / 2; j++) acc[j] = 0ull;

    const float4* xr = (const float4*)(x + (size_t)row * F_IN);
    const ulonglong2* sw2 = (const ulonglong2*)sW;  // 8 ull2 per k-step (32 floats)
#pragma unroll 2
    for (int k4 = 0; k4 < F_IN / 4; k4++) {
        float4 xv = __ldg(&xr[k4]);
        float xs[4] = {xv.x, xv.y, xv.z, xv.w};
#pragma unroll
        for (int s = 0; s < 4; s++) {
            unsigned long long xx;
            asm("mov.b64 %0, {%1, %1};" : "=l"(xx) : "f"(xs[s]));
            const ulonglong2* wk = &sw2[(k4 * 4 + s) * 8];
#pragma unroll
            for (int j = 0; j < 8; j++) {
                ulonglong2 wv = wk[j];  // LDS.128 broadcast
                asm("fma.rn.f32x2 %0, %1, %2, %0;" : "+l"(acc[2 * j])     : "l"(wv.x), "l"(xx));
                asm("fma.rn.f32x2 %0, %1, %2, %0;" : "+l"(acc[2 * j + 1]) : "l"(wv.y), "l"(xx));
            }
        }
    }
    __half2 h[C1 / 2];
#pragma unroll
    for (int j = 0; j < C1 / 2; j++) {
        float f0, f1;
        asm("mov.b64 {%0, %1}, %2;" : "=f"(f0), "=f"(f1) : "l"(acc[j]));
        h[j] = __floats2half2_rn(f0, f1);
    }
    uint4* o = (uint4*)&g_H1[(size_t)row * C1];
#pragma unroll
    for (int q = 0; q < 4; q++) o[q] = ((uint4*)h)[q];
}

__device__ __forceinline__ void red_add_v4(float* addr, float a, float b, float c, float d) {
    asm volatile("red.global.add.v4.f32 [%0], {%1, %2, %3, %4};"
                 :: "l"(addr), "f"(a), "f"(b), "f"(c), "f"(d) : "memory");
}

// ---------------- k4: scatter layer 1: out1[col] += norm * H1[row] ---------
// 8 lanes/edge; fp16 gather (LDG.64) -> fp32 RED.v4.
__global__ void k4_scatter1(int T) {
    int idx = blockIdx.x * blockDim.x + threadIdx.x;
    int e = idx >> 3;
    if (e >= T) return;
    int lane = idx & 7;
    int2 rc = g_rc[e];
    float nrm = g_norm[e];
    uint2 v = *(const uint2*)&g_H1[(size_t)rc.x * C1 + lane * 4];
    float2 f0 = __half22float2(*(__half2*)&v.x);
    float2 f1 = __half22float2(*(__half2*)&v.y);
    red_add_v4(&g_out1[(size_t)rc.y * C1 + lane * 4],
               nrm * f0.x, nrm * f0.y, nrm * f1.x, nrm * f1.y);
}

// ---------------- k5: H2 = fp16(relu(out1 + b1) @ W2) ----------------------
__global__ void k5_gemm2(const float* __restrict__ b1, const float* __restrict__ W2, int N) {
    __shared__ float sW[C1 * C2];
    __shared__ float sb[C1];
    for (int i = threadIdx.x; i < C1 * C2; i += blockDim.x) sW[i] = W2[i];
    if (threadIdx.x < C1) sb[threadIdx.x] = b1[threadIdx.x];
    __syncthreads();
    int row = blockIdx.x * blockDim.x + threadIdx.x;
    if (row >= N) return;
    const float4* in = (const float4*)&g_out1[(size_t)row * C1];
    float h[C1];
#pragma unroll
    for (int k4 = 0; k4 < C1 / 4; k4++) {
        float4 v = in[k4];
        h[4 * k4 + 0] = fmaxf(v.x + sb[4 * k4 + 0], 0.f);
        h[4 * k4 + 1] = fmaxf(v.y + sb[4 * k4 + 1], 0.f);
        h[4 * k4 + 2] = fmaxf(v.z + sb[4 * k4 + 2], 0.f);
        h[4 * k4 + 3] = fmaxf(v.w + sb[4 * k4 + 3], 0.f);
    }
    float acc[C2];
#pragma unroll
    for (int j = 0; j < C2; j++) acc[j] = 0.f;
#pragma unroll
    for (int k = 0; k < C1; k++) {
        const float* wk = &sW[k * C2];
#pragma unroll
        for (int j = 0; j < C2; j++) acc[j] += h[k] * wk[j];
    }
    __half2 hh[C2 / 2];
#pragma unroll
    for (int j = 0; j < C2 / 2; j++)
        hh[j] = __floats2half2_rn(acc[2 * j], acc[2 * j + 1]);
    uint4* o = (uint4*)&g_H2[(size_t)row * C2];
    o[0] = ((uint4*)hh)[0];
    o[1] = ((uint4*)hh)[1];
}

// ---------------- k6: scatter layer 2: out[col] += norm * H2[row] ----------
// 4 lanes/edge; fp16 gather (LDG.64) -> fp32 RED.v4.
__global__ void k6_scatter2(float* __restrict__ out, int T) {
    int idx = blockIdx.x * blockDim.x + threadIdx.x;
    int e = idx >> 2;
    if (e >= T) return;
    int lane = idx & 3;
    int2 rc = g_rc[e];
    float nrm = g_norm[e];
    uint2 v = *(const uint2*)&g_H2[(size_t)rc.x * C2 + lane * 4];
    float2 f0 = __half22float2(*(__half2*)&v.x);
    float2 f1 = __half22float2(*(__half2*)&v.y);
    red_add_v4(&out[(size_t)rc.y * C2 + lane * 4],
               nrm * f0.x, nrm * f0.y, nrm * f1.x, nrm * f1.y);
}

// ---------------- launch ----------------------------------------------------
extern "C" void kernel_launch(void* const* d_in, const int* in_sizes, int n_in,
                              void* d_out, int out_size) {
    const float* x  = (const float*)d_in[0];
    const void*  ei = d_in[1];
    const float* w  = (const float*)d_in[2];
    const float* W1 = (const float*)d_in[3];
    const float* b1 = (const float*)d_in[4];
    const float* W2 = (const float*)d_in[5];
    const float* b2 = (const float*)d_in[6];
    float* out = (float*)d_out;

    int N = in_sizes[0] / F_IN;
    int E = in_sizes[2];
    int T = E + N;

    k0_init<<<(N * C1 + 255) / 256, 256>>>(out, b2, (const int*)ei, N, E);
    k1_deg<<<(E + 255) / 256, 256>>>(ei, w, E);
    k2_pre<<<(T + 255) / 256, 256>>>(ei, w, E, N);
    k3_gemm1<<<(N + 255) / 256, 256>>>(x, W1, N);     // 4th launch -> profiled
    k4_scatter1<<<(T * 8 + 255) / 256, 256>>>(T);
    k5_gemm2<<<(N + 255) / 256, 256>>>(b1, W2, N);
    k6_scatter2<<<(T * 4 + 255) / 256, 256>>>(out, T);
}

// round 5
// speedup vs baseline: 1.4976x; 1.1076x over previous
#include <cuda_runtime.h>
#include <cuda_fp16.h>

#define NMAX 100000
#define EMAX 1600000
#define F_IN 256
#define C1 32
#define C2 16

// ---------------- scratch (device globals: allocation-free) ----------------
__device__ float  g_deg[NMAX];
__device__ int2   g_rc[EMAX + NMAX];
__device__ float  g_norm[EMAX + NMAX];
__device__ __half g_H1[(size_t)NMAX * C1];   // x @ W1, fp16
__device__ float  g_out1[(size_t)NMAX * C1]; // layer-1 aggregation, fp32
__device__ __half g_H2[(size_t)NMAX * C2];   // relu(out1+b1) @ W2, fp16
__device__ int    g_is64;

// ---------------- k0: init + parallel dtype detect -------------------------
__global__ void k0_init(float* __restrict__ out, const float* __restrict__ b2,
                        const int* __restrict__ ei32, int N, int E) {
    if (blockIdx.x == 0 && threadIdx.x < 32) {
        int ok = 1;
#pragma unroll
        for (int s = 0; s < 2; s++) {
            int idx = threadIdx.x + 32 * s;
            if (idx < E && idx < 64 && ei32[2 * idx + 1] != 0) ok = 0;
        }
        unsigned m = __ballot_sync(0xffffffffu, ok);
        if (threadIdx.x == 0) g_is64 = (m == 0xffffffffu) ? 1 : 0;
    }
    int i = blockIdx.x * blockDim.x + threadIdx.x;
    if (i < N * C1) g_out1[i] = 0.f;
    if (i < N)      g_deg[i]  = 0.f;
    if (i < N * C2) out[i]    = b2[i & (C2 - 1)];
}

// ---------------- k1: weighted in-degree -----------------------------------
__global__ void k1_deg(const void* __restrict__ ei, const float* __restrict__ w, int E) {
    int e = blockIdx.x * blockDim.x + threadIdx.x;
    if (e >= E) return;
    int c;
    if (g_is64) c = (int)((const long long*)ei)[(size_t)E + e];
    else        c = ((const int*)ei)[E + e];
    atomicAdd(&g_deg[c], w[e]);
}

// ---------------- k2: edge normalization (self loops as virtual edges) -----
__global__ void k2_pre(const void* __restrict__ ei, const float* __restrict__ w,
                       int E, int N) {
    int e = blockIdx.x * blockDim.x + threadIdx.x;
    if (e >= E + N) return;
    int r, c; float wt;
    if (e < E) {
        if (g_is64) {
            const long long* p = (const long long*)ei;
            r = (int)p[e]; c = (int)p[(size_t)E + e];
        } else {
            const int* p = (const int*)ei;
            r = p[e]; c = p[E + e];
        }
        wt = w[e];
    } else {
        r = c = e - E; wt = 1.f;
    }
    g_rc[e] = make_int2(r, c);
    g_norm[e] = rsqrtf(g_deg[r] + 1.f) * wt * rsqrtf(g_deg[c] + 1.f);
}

// ---------------- k3: GEMM1  H1 = fp16(x @ W1)  (4th launch -> profiled) ---
// Register tile 4 rows x 8 cols per thread. Per k: 2 broadcast LDS.128 of W
// amortized over 4 rows (16 FFMA2). x via LDG.128 once per row per k4.
// FMA-pipe floor ~43K cyc; L1 wavefronts ~40/k4/warp sit just above it.
__global__ void __launch_bounds__(256) k3_gemm1(const float* __restrict__ x,
                                                const float* __restrict__ W1, int N) {
    __shared__ float sW[F_IN * C1];  // 32 KB, layout [k][32]
    for (int i = threadIdx.x; i < F_IN * C1 / 4; i += 256)
        ((float4*)sW)[i] = __ldg((const float4*)W1 + i);
    __syncthreads();

    int cg   = threadIdx.x & 3;        // column group: cols cg*8 .. cg*8+7
    int rowg = threadIdx.x >> 2;       // 0..63
    int row0 = blockIdx.x * 256 + rowg * 4;
    if (row0 >= N) return;
    // clamped row indices for tail block (stores predicated separately)
    int r0 = row0, r1 = min(row0 + 1, N - 1), r2 = min(row0 + 2, N - 1), r3 = min(row0 + 3, N - 1);

    const float4* x0 = (const float4*)(x + (size_t)r0 * F_IN);
    const float4* x1 = (const float4*)(x + (size_t)r1 * F_IN);
    const float4* x2 = (const float4*)(x + (size_t)r2 * F_IN);
    const float4* x3 = (const float4*)(x + (size_t)r3 * F_IN);

    unsigned long long acc[4][4];
#pragma unroll
    for (int i = 0; i < 4; i++)
#pragma unroll
        for (int p = 0; p < 4; p++) acc[i][p] = 0ull;

    const float* wbase = &sW[cg * 8];
#pragma unroll 2
    for (int k4 = 0; k4 < F_IN / 4; k4++) {
        float4 a0 = __ldg(&x0[k4]);
        float4 a1 = __ldg(&x1[k4]);
        float4 a2 = __ldg(&x2[k4]);
        float4 a3 = __ldg(&x3[k4]);
#pragma unroll
        for (int s = 0; s < 4; s++) {
            const float* wk = wbase + (k4 * 4 + s) * C1;
            ulonglong2 wA = *(const ulonglong2*)wk;        // cols cg*8   .. cg*8+3
            ulonglong2 wB = *(const ulonglong2*)(wk + 4);  // cols cg*8+4 .. cg*8+7
            float xs0 = s == 0 ? a0.x : s == 1 ? a0.y : s == 2 ? a0.z : a0.w;
            float xs1 = s == 0 ? a1.x : s == 1 ? a1.y : s == 2 ? a1.z : a1.w;
            float xs2 = s == 0 ? a2.x : s == 1 ? a2.y : s == 2 ? a2.z : a2.w;
            float xs3 = s == 0 ? a3.x : s == 1 ? a3.y : s == 2 ? a3.z : a3.w;
            unsigned long long xx0, xx1, xx2, xx3;
            asm("mov.b64 %0, {%1, %1};" : "=l"(xx0) : "f"(xs0));
            asm("mov.b64 %0, {%1, %1};" : "=l"(xx1) : "f"(xs1));
            asm("mov.b64 %0, {%1, %1};" : "=l"(xx2) : "f"(xs2));
            asm("mov.b64 %0, {%1, %1};" : "=l"(xx3) : "f"(xs3));
            asm("fma.rn.f32x2 %0, %1, %2, %0;" : "+l"(acc[0][0]) : "l"(wA.x), "l"(xx0));
            asm("fma.rn.f32x2 %0, %1, %2, %0;" : "+l"(acc[0][1]) : "l"(wA.y), "l"(xx0));
            asm("fma.rn.f32x2 %0, %1, %2, %0;" : "+l"(acc[0][2]) : "l"(wB.x), "l"(xx0));
            asm("fma.rn.f32x2 %0, %1, %2, %0;" : "+l"(acc[0][3]) : "l"(wB.y), "l"(xx0));
            asm("fma.rn.f32x2 %0, %1, %2, %0;" : "+l"(acc[1][0]) : "l"(wA.x), "l"(xx1));
            asm("fma.rn.f32x2 %0, %1, %2, %0;" : "+l"(acc[1][1]) : "l"(wA.y), "l"(xx1));
            asm("fma.rn.f32x2 %0, %1, %2, %0;" : "+l"(acc[1][2]) : "l"(wB.x), "l"(xx1));
            asm("fma.rn.f32x2 %0, %1, %2, %0;" : "+l"(acc[1][3]) : "l"(wB.y), "l"(xx1));
            asm("fma.rn.f32x2 %0, %1, %2, %0;" : "+l"(acc[2][0]) : "l"(wA.x), "l"(xx2));
            asm("fma.rn.f32x2 %0, %1, %2, %0;" : "+l"(acc[2][1]) : "l"(wA.y), "l"(xx2));
            asm("fma.rn.f32x2 %0, %1, %2, %0;" : "+l"(acc[2][2]) : "l"(wB.x), "l"(xx2));
            asm("fma.rn.f32x2 %0, %1, %2, %0;" : "+l"(acc[2][3]) : "l"(wB.y), "l"(xx2));
            asm("fma.rn.f32x2 %0, %1, %2, %0;" : "+l"(acc[3][0]) : "l"(wA.x), "l"(xx3));
            asm("fma.rn.f32x2 %0, %1, %2, %0;" : "+l"(acc[3][1]) : "l"(wA.y), "l"(xx3));
            asm("fma.rn.f32x2 %0, %1, %2, %0;" : "+l"(acc[3][2]) : "l"(wB.x), "l"(xx3));
            asm("fma.rn.f32x2 %0, %1, %2, %0;" : "+l"(acc[3][3]) : "l"(wB.y), "l"(xx3));
        }
    }
#pragma unroll
    for (int i = 0; i < 4; i++) {
        if (row0 + i >= N) break;
        __half2 h[4];
#pragma unroll
        for (int p = 0; p < 4; p++) {
            float f0, f1;
            asm("mov.b64 {%0, %1}, %2;" : "=f"(f0), "=f"(f1) : "l"(acc[i][p]));
            h[p] = __floats2half2_rn(f0, f1);
        }
        *(uint4*)&g_H1[(size_t)(row0 + i) * C1 + cg * 8] = *(uint4*)h;
    }
}

__device__ __forceinline__ void red_add_v4(float* addr, float a, float b, float c, float d) {
    asm volatile("red.global.add.v4.f32 [%0], {%1, %2, %3, %4};"
                 :: "l"(addr), "f"(a), "f"(b), "f"(c), "f"(d) : "memory");
}

// ---------------- k4: scatter layer 1: out1[col] += norm * H1[row] ---------
__global__ void k4_scatter1(int T) {
    int idx = blockIdx.x * blockDim.x + threadIdx.x;
    int e = idx >> 3;
    if (e >= T) return;
    int lane = idx & 7;
    int2 rc = g_rc[e];
    float nrm = g_norm[e];
    uint2 v = *(const uint2*)&g_H1[(size_t)rc.x * C1 + lane * 4];
    float2 f0 = __half22float2(*(__half2*)&v.x);
    float2 f1 = __half22float2(*(__half2*)&v.y);
    red_add_v4(&g_out1[(size_t)rc.y * C1 + lane * 4],
               nrm * f0.x, nrm * f0.y, nrm * f1.x, nrm * f1.y);
}

// ---------------- k5: H2 = fp16(relu(out1 + b1) @ W2) ----------------------
__global__ void k5_gemm2(const float* __restrict__ b1, const float* __restrict__ W2, int N) {
    __shared__ float sW[C1 * C2];
    __shared__ float sb[C1];
    for (int i = threadIdx.x; i < C1 * C2; i += blockDim.x) sW[i] = W2[i];
    if (threadIdx.x < C1) sb[threadIdx.x] = b1[threadIdx.x];
    __syncthreads();
    int row = blockIdx.x * blockDim.x + threadIdx.x;
    if (row >= N) return;
    const float4* in = (const float4*)&g_out1[(size_t)row * C1];
    float h[C1];
#pragma unroll
    for (int k4 = 0; k4 < C1 / 4; k4++) {
        float4 v = in[k4];
        h[4 * k4 + 0] = fmaxf(v.x + sb[4 * k4 + 0], 0.f);
        h[4 * k4 + 1] = fmaxf(v.y + sb[4 * k4 + 1], 0.f);
        h[4 * k4 + 2] = fmaxf(v.z + sb[4 * k4 + 2], 0.f);
        h[4 * k4 + 3] = fmaxf(v.w + sb[4 * k4 + 3], 0.f);
    }
    float acc[C2];
#pragma unroll
    for (int j = 0; j < C2; j++) acc[j] = 0.f;
#pragma unroll
    for (int k = 0; k < C1; k++) {
        const float* wk = &sW[k * C2];
#pragma unroll
        for (int j = 0; j < C2; j++) acc[j] += h[k] * wk[j];
    }
    __half2 hh[C2 / 2];
#pragma unroll
    for (int j = 0; j < C2 / 2; j++)
        hh[j] = __floats2half2_rn(acc[2 * j], acc[2 * j + 1]);
    uint4* o = (uint4*)&g_H2[(size_t)row * C2];
    o[0] = ((uint4*)hh)[0];
    o[1] = ((uint4*)hh)[1];
}

// ---------------- k6: scatter layer 2: out[col] += norm * H2[row] ----------
__global__ void k6_scatter2(float* __restrict__ out, int T) {
    int idx = blockIdx.x * blockDim.x + threadIdx.x;
    int e = idx >> 2;
    if (e >= T) return;
    int lane = idx & 3;
    int2 rc = g_rc[e];
    float nrm = g_norm[e];
    uint2 v = *(const uint2*)&g_H2[(size_t)rc.x * C2 + lane * 4];
    float2 f0 = __half22float2(*(__half2*)&v.x);
    float2 f1 = __half22float2(*(__half2*)&v.y);
    red_add_v4(&out[(size_t)rc.y * C2 + lane * 4],
               nrm * f0.x, nrm * f0.y, nrm * f1.x, nrm * f1.y);
}

// ---------------- launch ----------------------------------------------------
extern "C" void kernel_launch(void* const* d_in, const int* in_sizes, int n_in,
                              void* d_out, int out_size) {
    const float* x  = (const float*)d_in[0];
    const void*  ei = d_in[1];
    const float* w  = (const float*)d_in[2];
    const float* W1 = (const float*)d_in[3];
    const float* b1 = (const float*)d_in[4];
    const float* W2 = (const float*)d_in[5];
    const float* b2 = (const float*)d_in[6];
    float* out = (float*)d_out;

    int N = in_sizes[0] / F_IN;
    int E = in_sizes[2];
    int T = E + N;

    k0_init<<<(N * C1 + 255) / 256, 256>>>(out, b2, (const int*)ei, N, E);
    k1_deg<<<(E + 255) / 256, 256>>>(ei, w, E);
    k2_pre<<<(T + 255) / 256, 256>>>(ei, w, E, N);
    k3_gemm1<<<(N + 255) / 256, 256>>>(x, W1, N);     // 4th launch -> profiled
    k4_scatter1<<<(T * 8 + 255) / 256, 256>>>(T);
    k5_gemm2<<<(N + 255) / 256, 256>>>(b1, W2, N);
    k6_scatter2<<<(T * 4 + 255) / 256, 256>>>(out, T);
}

// round 6
// speedup vs baseline: 1.5374x; 1.0266x over previous
#include <cuda_runtime.h>
#include <cuda_fp16.h>

#define NMAX 100000
#define EMAX 1600000
#define F_IN 256
#define C1 32
#define C2 16
#define RPB 256   // rows per block in gemm1

// ---------------- scratch (device globals: allocation-free) ----------------
__device__ float  g_deg[NMAX];
__device__ int2   g_rc[EMAX + NMAX];
__device__ float  g_norm[EMAX + NMAX];
__device__ __half g_H1[(size_t)NMAX * C1];   // x @ W1, fp16
__device__ float  g_out1[(size_t)NMAX * C1]; // layer-1 aggregation, fp32
__device__ __half g_H2[(size_t)NMAX * C2];   // relu(out1+b1) @ W2, fp16
__device__ int    g_is64;

// ---------------- k0: init + parallel dtype detect -------------------------
__global__ void k0_init(float* __restrict__ out, const float* __restrict__ b2,
                        const int* __restrict__ ei32, int N, int E) {
    if (blockIdx.x == 0 && threadIdx.x < 32) {
        int ok = 1;
#pragma unroll
        for (int s = 0; s < 2; s++) {
            int idx = threadIdx.x + 32 * s;
            if (idx < E && idx < 64 && ei32[2 * idx + 1] != 0) ok = 0;
        }
        unsigned m = __ballot_sync(0xffffffffu, ok);
        if (threadIdx.x == 0) g_is64 = (m == 0xffffffffu) ? 1 : 0;
    }
    int i = blockIdx.x * blockDim.x + threadIdx.x;
    if (i < N * C1) g_out1[i] = 0.f;
    if (i < N)      g_deg[i]  = 0.f;
    if (i < N * C2) out[i]    = b2[i & (C2 - 1)];
}

// ---------------- k1: weighted in-degree -----------------------------------
__global__ void k1_deg(const void* __restrict__ ei, const float* __restrict__ w, int E) {
    int e = blockIdx.x * blockDim.x + threadIdx.x;
    if (e >= E) return;
    int c;
    if (g_is64) c = (int)((const long long*)ei)[(size_t)E + e];
    else        c = ((const int*)ei)[E + e];
    atomicAdd(&g_deg[c], w[e]);
}

// ---------------- k2: edge normalization (self loops as virtual edges) -----
__global__ void k2_pre(const void* __restrict__ ei, const float* __restrict__ w,
                       int E, int N) {
    int e = blockIdx.x * blockDim.x + threadIdx.x;
    if (e >= E + N) return;
    int r, c; float wt;
    if (e < E) {
        if (g_is64) {
            const long long* p = (const long long*)ei;
            r = (int)p[e]; c = (int)p[(size_t)E + e];
        } else {
            const int* p = (const int*)ei;
            r = p[e]; c = p[E + e];
        }
        wt = w[e];
    } else {
        r = c = e - E; wt = 1.f;
    }
    g_rc[e] = make_int2(r, c);
    g_norm[e] = rsqrtf(g_deg[r] + 1.f) * wt * rsqrtf(g_deg[c] + 1.f);
}

// ---------------- k3: GEMM1  H1 = fp16(x @ W1)  (4th launch -> profiled) ---
// 256 rows/block. x staged per 32-wide k-tile into smem (coalesced LDG.128,
// XOR bank swizzle). Thread tile: 4 rows (stride 64) x 8 cols, fma.rn.f32x2.
__global__ void __launch_bounds__(256) k3_gemm1(const float* __restrict__ x,
                                                const float* __restrict__ W1, int N) {
    __shared__ float sW[F_IN * C1];   // 32 KB, [k][32]
    __shared__ float sX[RPB * 32];    // 32 KB, one k-tile, xor-swizzled float4s
    int tid = threadIdx.x;
    for (int i = tid; i < F_IN * C1 / 4; i += 256)
        ((float4*)sW)[i] = __ldg((const float4*)W1 + i);

    int cg   = tid & 3;          // cols cg*8 .. cg*8+7
    int rowg = tid >> 2;         // 0..63; thread rows: rowg + 64*i
    int base = blockIdx.x * RPB;

    unsigned long long acc[4][4];
#pragma unroll
    for (int i = 0; i < 4; i++)
#pragma unroll
        for (int p = 0; p < 4; p++) acc[i][p] = 0ull;

    const float* wbase = &sW[cg * 8];
    float4* sX4 = (float4*)sX;

    for (int t = 0; t < F_IN / 32; t++) {   // 8 k-tiles of 32 floats
        __syncthreads();                    // previous tile's reads done
        // stage 256 rows x 8 float4 (coalesced: lanes -> consecutive 16B)
#pragma unroll
        for (int i = 0; i < 8; i++) {
            int idx = tid + 256 * i;
            int row = idx >> 3, kq = idx & 7;
            int grow = min(base + row, N - 1);
            float4 v = __ldg((const float4*)x + (size_t)grow * (F_IN / 4) + t * 8 + kq);
            sX4[row * 8 + (kq ^ (row & 7))] = v;
        }
        __syncthreads();
#pragma unroll
        for (int k4 = 0; k4 < 8; k4++) {
            float4 a[4];
#pragma unroll
            for (int i = 0; i < 4; i++) {
                int row = rowg + 64 * i;
                a[i] = sX4[row * 8 + (k4 ^ (row & 7))];  // conflict-free via xor
            }
#pragma unroll
            for (int s = 0; s < 4; s++) {
                const float* wk = wbase + (t * 32 + k4 * 4 + s) * C1;
                ulonglong2 wA = *(const ulonglong2*)wk;        // cols +0..3
                ulonglong2 wB = *(const ulonglong2*)(wk + 4);  // cols +4..7
#pragma unroll
                for (int i = 0; i < 4; i++) {
                    float xs = s == 0 ? a[i].x : s == 1 ? a[i].y : s == 2 ? a[i].z : a[i].w;
                    unsigned long long xx;
                    asm("mov.b64 %0, {%1, %1};" : "=l"(xx) : "f"(xs));
                    asm("fma.rn.f32x2 %0, %1, %2, %0;" : "+l"(acc[i][0]) : "l"(wA.x), "l"(xx));
                    asm("fma.rn.f32x2 %0, %1, %2, %0;" : "+l"(acc[i][1]) : "l"(wA.y), "l"(xx));
                    asm("fma.rn.f32x2 %0, %1, %2, %0;" : "+l"(acc[i][2]) : "l"(wB.x), "l"(xx));
                    asm("fma.rn.f32x2 %0, %1, %2, %0;" : "+l"(acc[i][3]) : "l"(wB.y), "l"(xx));
                }
            }
        }
    }
#pragma unroll
    for (int i = 0; i < 4; i++) {
        int grow = base + rowg + 64 * i;
        if (grow >= N) continue;
        __half2 h[4];
#pragma unroll
        for (int p = 0; p < 4; p++) {
            float f0, f1;
            asm("mov.b64 {%0, %1}, %2;" : "=f"(f0), "=f"(f1) : "l"(acc[i][p]));
            h[p] = __floats2half2_rn(f0, f1);
        }
        *(uint4*)&g_H1[(size_t)grow * C1 + cg * 8] = *(uint4*)h;
    }
}

__device__ __forceinline__ void red_add_v4(float* addr, float a, float b, float c, float d) {
    asm volatile("red.global.add.v4.f32 [%0], {%1, %2, %3, %4};"
                 :: "l"(addr), "f"(a), "f"(b), "f"(c), "f"(d) : "memory");
}

// ---------------- k4: scatter layer 1: out1[col] += norm * H1[row] ---------
__global__ void k4_scatter1(int T) {
    int idx = blockIdx.x * blockDim.x + threadIdx.x;
    int e = idx >> 3;
    if (e >= T) return;
    int lane = idx & 7;
    int2 rc = g_rc[e];
    float nrm = g_norm[e];
    uint2 v = *(const uint2*)&g_H1[(size_t)rc.x * C1 + lane * 4];
    float2 f0 = __half22float2(*(__half2*)&v.x);
    float2 f1 = __half22float2(*(__half2*)&v.y);
    red_add_v4(&g_out1[(size_t)rc.y * C1 + lane * 4],
               nrm * f0.x, nrm * f0.y, nrm * f1.x, nrm * f1.y);
}

// ---------------- k5: H2 = fp16(relu(out1 + b1) @ W2) ----------------------
__global__ void k5_gemm2(const float* __restrict__ b1, const float* __restrict__ W2, int N) {
    __shared__ float sW[C1 * C2];
    __shared__ float sb[C1];
    for (int i = threadIdx.x; i < C1 * C2; i += blockDim.x) sW[i] = W2[i];
    if (threadIdx.x < C1) sb[threadIdx.x] = b1[threadIdx.x];
    __syncthreads();
    int row = blockIdx.x * blockDim.x + threadIdx.x;
    if (row >= N) return;
    const float4* in = (const float4*)&g_out1[(size_t)row * C1];
    float h[C1];
#pragma unroll
    for (int k4 = 0; k4 < C1 / 4; k4++) {
        float4 v = in[k4];
        h[4 * k4 + 0] = fmaxf(v.x + sb[4 * k4 + 0], 0.f);
        h[4 * k4 + 1] = fmaxf(v.y + sb[4 * k4 + 1], 0.f);
        h[4 * k4 + 2] = fmaxf(v.z + sb[4 * k4 + 2], 0.f);
        h[4 * k4 + 3] = fmaxf(v.w + sb[4 * k4 + 3], 0.f);
    }
    float acc[C2];
#pragma unroll
    for (int j = 0; j < C2; j++) acc[j] = 0.f;
#pragma unroll
    for (int k = 0; k < C1; k++) {
        const float* wk = &sW[k * C2];
#pragma unroll
        for (int j = 0; j < C2; j++) acc[j] += h[k] * wk[j];
    }
    __half2 hh[C2 / 2];
#pragma unroll
    for (int j = 0; j < C2 / 2; j++)
        hh[j] = __floats2half2_rn(acc[2 * j], acc[2 * j + 1]);
    uint4* o = (uint4*)&g_H2[(size_t)row * C2];
    o[0] = ((uint4*)hh)[0];
    o[1] = ((uint4*)hh)[1];
}

// ---------------- k6: scatter layer 2: out[col] += norm * H2[row] ----------
__global__ void k6_scatter2(float* __restrict__ out, int T) {
    int idx = blockIdx.x * blockDim.x + threadIdx.x;
    int e = idx >> 2;
    if (e >= T) return;
    int lane = idx & 3;
    int2 rc = g_rc[e];
    float nrm = g_norm[e];
    uint2 v = *(const uint2*)&g_H2[(size_t)rc.x * C2 + lane * 4];
    float2 f0 = __half22float2(*(__half2*)&v.x);
    float2 f1 = __half22float2(*(__half2*)&v.y);
    red_add_v4(&out[(size_t)rc.y * C2 + lane * 4],
               nrm * f0.x, nrm * f0.y, nrm * f1.x, nrm * f1.y);
}

// ---------------- launch ----------------------------------------------------
extern "C" void kernel_launch(void* const* d_in, const int* in_sizes, int n_in,
                              void* d_out, int out_size) {
    const float* x  = (const float*)d_in[0];
    const void*  ei = d_in[1];
    const float* w  = (const float*)d_in[2];
    const float* W1 = (const float*)d_in[3];
    const float* b1 = (const float*)d_in[4];
    const float* W2 = (const float*)d_in[5];
    const float* b2 = (const float*)d_in[6];
    float* out = (float*)d_out;

    int N = in_sizes[0] / F_IN;
    int E = in_sizes[2];
    int T = E + N;

    k0_init<<<(N * C1 + 255) / 256, 256>>>(out, b2, (const int*)ei, N, E);
    k1_deg<<<(E + 255) / 256, 256>>>(ei, w, E);
    k2_pre<<<(T + 255) / 256, 256>>>(ei, w, E, N);
    k3_gemm1<<<(N + RPB - 1) / RPB, 256>>>(x, W1, N);  // 4th launch -> profiled
    k4_scatter1<<<(T * 8 + 255) / 256, 256>>>(T);
    k5_gemm2<<<(N + 255) / 256, 256>>>(b1, W2, N);
    k6_scatter2<<<(T * 4 + 255) / 256, 256>>>(out, T);
}